// round 3
// baseline (speedup 1.0000x reference)
#include <cuda_runtime.h>

// Problem shape (fixed by the dataset)
#define W_  1920
#define H_  1080
#define B_  4
#define C_  3
constexpr int HW = H_ * W_;     // 2,073,600
constexpr int N  = B_ * HW;     // 8,294,400

// Scratch (cudaMalloc forbidden -> static device globals, zero-initialized at load).
// INVARIANT: g_dbuf is all-zero and g_acc is all-zero at entry of every
// kernel_launch call. g_acc is re-zeroed by k_depth (fused stream store),
// g_dbuf is re-zeroed by the tail of k_norm. First call uses the loader zeros.
__device__ int                  g_dbuf[N];   // quantized motion-magnitude depth buffer
__device__ __align__(16) float4 g_acc[N];    // AoS: {weight, c0, c1, c2} per pixel

// One 16-byte vector reduction instead of 4 scalar float atomics.
__device__ __forceinline__ void red_add_v4(float4* p, float a, float b, float c, float d)
{
    asm volatile("red.global.add.v4.f32 [%0], {%1, %2, %3, %4};"
                 :: "l"(p), "f"(a), "f"(b), "f"(c), "f"(d) : "memory");
}

__device__ __forceinline__ int depth_key(float fx, float fy)
{
    // round-half-even (matches jnp.round), IEEE sqrt regardless of fast-math
    return __float2int_rn(__fsqrt_rn(fx * fx + fy * fy) * 1000.0f);
}

// ---------------------------------------------------------------------------
// Pass 1: scatter-max depth buffer + stream-zero the accumulator.
// 2 pixels per thread (W is even -> a pixel pair never splits a row).
// All 4 in-bounds corners participate regardless of bilinear weight --
// a zero-weight corner can still suppress other pixels' contributions.
// ---------------------------------------------------------------------------
__device__ __forceinline__ void depth_pixel(float fx, float fy, int w, int h, int base)
{
    float x = (float)w + fx;
    float y = (float)h + fy;
    int x0 = (int)floorf(x);
    int y0 = (int)floorf(y);
    int d  = depth_key(fx, fy);
#pragma unroll
    for (int dy = 0; dy < 2; dy++) {
#pragma unroll
        for (int dx = 0; dx < 2; dx++) {
            int tx = x0 + dx;
            int ty = y0 + dy;
            if (tx >= 0 && tx < W_ && ty >= 0 && ty < H_)
                atomicMax(&g_dbuf[base + ty * W_ + tx], d);
        }
    }
}

__global__ void __launch_bounds__(256) k_depth(const float4* __restrict__ flow4)
{
    int t = blockIdx.x * blockDim.x + threadIdx.x;
    if (t >= N / 2) return;
    int i = t * 2;

    // fused accumulator zeroing (2x STG.128, rides the store path)
    const float4 z = make_float4(0.f, 0.f, 0.f, 0.f);
    g_acc[i]     = z;
    g_acc[i + 1] = z;

    int b = i / HW;
    int p = i - b * HW;
    int h = p / W_;
    int w = p - h * W_;

    float4 ff = flow4[t];           // {fx0, fy0, fx1, fy1} for pixels i, i+1
    int base = b * HW;
    depth_pixel(ff.x, ff.y, w,     h, base);
    depth_pixel(ff.z, ff.w, w + 1, h, base);
}

// ---------------------------------------------------------------------------
// Pass 2: accumulate depth-test winners, ONE vec4 reduction per winning corner.
// 2 pixels per thread.
// ---------------------------------------------------------------------------
__device__ __forceinline__ void accum_pixel(float fx, float fy, int w, int h, int base,
                                            float v0, float v1, float v2)
{
    float x = (float)w + fx;
    float y = (float)h + fy;
    float x0f = floorf(x);
    float y0f = floorf(y);
    float ax = x - x0f;
    float ay = y - y0f;
    int x0 = (int)x0f;
    int y0 = (int)y0f;
    int d  = depth_key(fx, fy);

    float wx1 = ax, wx0 = 1.0f - ax;
    float wy1 = ay, wy0 = 1.0f - ay;
    float wts[4] = { wx0 * wy0, wx1 * wy0, wx0 * wy1, wx1 * wy1 };
    int   txs[4] = { x0, x0 + 1, x0,     x0 + 1 };
    int   tys[4] = { y0, y0,     y0 + 1, y0 + 1 };

#pragma unroll
    for (int k = 0; k < 4; k++) {
        int tx = txs[k];
        int ty = tys[k];
        if (tx < 0 || tx >= W_ || ty < 0 || ty >= H_) continue;
        int idx = base + ty * W_ + tx;
        if (__ldg(&g_dbuf[idx]) != d) continue;   // depth test (d >= 0 always)
        float wv = wts[k];
        if (wv == 0.0f) continue;                 // adding exact 0.0 is an identity
        red_add_v4(&g_acc[idx], wv, wv * v0, wv * v1, wv * v2);
    }
}

__global__ void __launch_bounds__(256) k_accum(const float* __restrict__ im0,
                                               const float4* __restrict__ flow4)
{
    int t = blockIdx.x * blockDim.x + threadIdx.x;
    if (t >= N / 2) return;
    int i = t * 2;

    int b = i / HW;
    int p = i - b * HW;
    int h = p / W_;
    int w = p - h * W_;

    float4 ff = flow4[t];

    // source pixel values: 2 adjacent pixels x 3 planar channels (LDG.64 each)
    const float* src = im0 + (size_t)b * 3 * HW + p;   // p even -> 8B aligned
    float2 s0 = __ldg(reinterpret_cast<const float2*>(src));
    float2 s1 = __ldg(reinterpret_cast<const float2*>(src + HW));
    float2 s2 = __ldg(reinterpret_cast<const float2*>(src + 2 * HW));

    int base = b * HW;
    accum_pixel(ff.x, ff.y, w,     h, base, s0.x, s1.x, s2.x);
    accum_pixel(ff.z, ff.w, w + 1, h, base, s0.y, s1.y, s2.y);
}

// ---------------------------------------------------------------------------
// Pass 3: normalize (4 pixels/thread) + re-zero g_dbuf for the next call.
// out[b][c][h][w] = acc.c / max(acc.w, eps)
// ---------------------------------------------------------------------------
__global__ void __launch_bounds__(256) k_norm(float* __restrict__ out)
{
    int t = blockIdx.x * blockDim.x + threadIdx.x;
    if (t >= N / 4) return;

    int i = t * 4;            // first pixel of this group (HW % 4 == 0 -> same b)
    int b = i / HW;
    int p = i - b * HW;

    float4 a0 = g_acc[i];
    float4 a1 = g_acc[i + 1];
    float4 a2 = g_acc[i + 2];
    float4 a3 = g_acc[i + 3];

    // re-zero depth buffer for next kernel_launch call (deterministic: loader
    // zeros on first call, this store on all subsequent calls)
    reinterpret_cast<int4*>(g_dbuf)[t] = make_int4(0, 0, 0, 0);

    float r0 = 1.0f / fmaxf(a0.x, 1e-5f);
    float r1 = 1.0f / fmaxf(a1.x, 1e-5f);
    float r2 = 1.0f / fmaxf(a2.x, 1e-5f);
    float r3 = 1.0f / fmaxf(a3.x, 1e-5f);

    float* dst = out + (size_t)b * 3 * HW + p;    // p % 4 == 0 -> 16B aligned
    reinterpret_cast<float4*>(dst)[0]          = make_float4(a0.y * r0, a1.y * r1, a2.y * r2, a3.y * r3);
    reinterpret_cast<float4*>(dst + HW)[0]     = make_float4(a0.z * r0, a1.z * r1, a2.z * r2, a3.z * r3);
    reinterpret_cast<float4*>(dst + 2 * HW)[0] = make_float4(a0.w * r0, a1.w * r1, a2.w * r2, a3.w * r3);
}

// ---------------------------------------------------------------------------
extern "C" void kernel_launch(void* const* d_in, const int* in_sizes, int n_in,
                              void* d_out, int out_size)
{
    const float*  im0   = (const float*)d_in[0];   // [B,C,H,W] float32
    const float4* flow4 = (const float4*)d_in[1];  // [B,H,W,2] float32, 2 px per float4
    float*        out   = (float*)d_out;           // [B,C,H,W] float32

    const int T = 256;
    k_depth<<<(N / 2 + T - 1) / T, T>>>(flow4);
    k_accum<<<(N / 2 + T - 1) / T, T>>>(im0, flow4);
    k_norm <<<(N / 4 + T - 1) / T, T>>>(out);

    (void)in_sizes; (void)n_in; (void)out_size;
}